// round 16
// baseline (speedup 1.0000x reference)
#include <cuda_runtime.h>
#include <cuda_fp16.h>
#include <cstdint>

// Problem constants
#define NB   16
#define CC   128
#define HH   112
#define WW   112
#define PLANE (HH*WW)          // 12544 pixels per plane
#define PTS   (98*16*16)       // 25088 sample points per image
#define THREADS 512
#define PAIR_ITERS 24          // 24*512 pairs; tail = 256 pairs
#define TAIL_PAIRS 256

// Precomputed per-point records: {b00, half2(wx,wy)} — 3.2 MB
__device__ uint2 g_recs[(size_t)NB * PTS];

static __device__ __forceinline__ unsigned int h2u(__half2 h)
{ union { __half2 h; unsigned int u; } c; c.h = h; return c.u; }
static __device__ __forceinline__ __half2 u2h(unsigned int u)
{ union { __half2 h; unsigned int u; } c; c.u = u; return c.h; }
static __device__ __forceinline__ float unn(float v)
{ return fminf(fmaxf(fmaf(v + 1.0f, 56.0f, -0.5f), 0.0f), 111.0f); }

// ---------------- Prepass: grid -> {b00, half2(wx,wy)} records --------------
__global__ __launch_bounds__(512, 4)
void prepass_kernel(const float* __restrict__ grid)
{
    const int j = blockIdx.x * 512 + threadIdx.x;      // 0 .. NB*PTS-1
    const float2 xy = reinterpret_cast<const float2*>(grid)[j];
    const float x = unn(xy.x), y = unn(xy.y);
    const int x0 = min((int)x, WW - 2);
    const int y0 = min((int)y, HH - 2);
    const float wx = x - (float)x0;
    const float wy = y - (float)y0;
    g_recs[j] = make_uint2((unsigned int)(y0 * WW + x0),
                           h2u(__floats2half2_rn(wx, wy)));
}

static __device__ __forceinline__ __half2 bilerp_rec(const __half2* __restrict__ s,
                                                     unsigned int b00u,
                                                     unsigned int wbits)
{
    const int b00 = (int)b00u;
    const __half2 w = u2h(wbits);
    const __half2 wx2 = __half2half2(__low2half(w));
    const __half2 wy2 = __half2half2(__high2half(w));

    const __half2 q00 = s[b00];
    const __half2 q01 = s[b00 + 1];
    const __half2 q10 = s[b00 + WW];
    const __half2 q11 = s[b00 + WW + 1];

    const __half2 top = __hfma2(wx2, __hsub2(q01, q00), q00);
    const __half2 bot = __hfma2(wx2, __hsub2(q11, q10), q10);
    return __hfma2(wy2, __hsub2(bot, top), top);
}

// ---------------- Sample: R12 structure, record-driven ----------------------
__global__ __launch_bounds__(THREADS, 3)
void patches_kernel(const float* __restrict__ fm,
                    float* __restrict__ out)
{
    extern __shared__ __half2 s[];   // PLANE half2 (50,176 B)

    const int n  = blockIdx.x >> 6;          // 16 images
    const int c0 = (blockIdx.x & 63) * 2;    // 64 channel pairs

    // ---- Stage 2 channel planes packed as half2 (LDG.128 x2 + STS.128) ----
    {
        const float4* __restrict__ pa =
            reinterpret_cast<const float4*>(fm + ((size_t)n * CC + c0) * PLANE);
        const float4* __restrict__ pb = pa + PLANE / 4;
        uint4* __restrict__ sd = reinterpret_cast<uint4*>(s);
        #pragma unroll
        for (int i = threadIdx.x; i < PLANE / 4; i += THREADS) {
            const float4 a = pa[i];
            const float4 b = pb[i];
            uint4 v;
            v.x = h2u(__floats2half2_rn(a.x, b.x));
            v.y = h2u(__floats2half2_rn(a.y, b.y));
            v.z = h2u(__floats2half2_rn(a.z, b.z));
            v.w = h2u(__floats2half2_rn(a.w, b.w));
            sd[i] = v;
        }
    }
    __syncthreads();

    const int t = threadIdx.x;

    // Paired records: one uint4 = two points (2q, 2q+1), adjacent pix.
    const uint4* __restrict__ r4 =
        reinterpret_cast<const uint4*>(g_recs) + (size_t)n * (PTS / 2) + t;

    // out[n, p, c, hg, wg]  flat = ((n*98 + p)*128 + c)*256 + pix
    float* __restrict__ ob = out + (((size_t)n * 98) * CC + c0) * 256;
    float* __restrict__ o = ob + (t >> 7) * (CC * 256) + ((2 * t) & 255);

    #pragma unroll 4
    for (int i = 0; i < PAIR_ITERS; i++) {
        const uint4 rec = r4[i * THREADS];       // points 2q, 2q+1

        const __half2 rA = bilerp_rec(s, rec.x, rec.y);
        const __half2 rB = bilerp_rec(s, rec.z, rec.w);

        const float2 fA = __half22float2(rA);
        const float2 fB = __half22float2(rB);

        float* __restrict__ oi = o + i * (4 * CC * 256);
        *reinterpret_cast<float2*>(oi)       = make_float2(fA.x, fB.x);
        *reinterpret_cast<float2*>(oi + 256) = make_float2(fA.y, fB.y);
    }

    // Tail: 256 pairs, q = 12288 + t (t < 256)
    if (t < TAIL_PAIRS) {
        const uint4 rec = r4[PAIR_ITERS * THREADS];

        const __half2 rA = bilerp_rec(s, rec.x, rec.y);
        const __half2 rB = bilerp_rec(s, rec.z, rec.w);

        const float2 fA = __half22float2(rA);
        const float2 fB = __half22float2(rB);

        // p = 96 + (t>>7), pix = (2t) & 255
        float* __restrict__ ot = ob + (96 + (t >> 7)) * (CC * 256) + ((2 * t) & 255);
        *reinterpret_cast<float2*>(ot)       = make_float2(fA.x, fB.x);
        *reinterpret_cast<float2*>(ot + 256) = make_float2(fA.y, fB.y);
    }
}

extern "C" void kernel_launch(void* const* d_in, const int* in_sizes, int n_in,
                              void* d_out, int out_size)
{
    const float* fm   = (const float*)d_in[0];   // [16,128,112,112] f32
    const float* grid = (const float*)d_in[1];   // [16,98,16,16,2]  f32
    float* out        = (float*)d_out;           // [16,98,128,16,16] f32

    const int smem = PLANE * sizeof(__half2);    // 50,176 B
    cudaFuncSetAttribute(patches_kernel,
                         cudaFuncAttributeMaxDynamicSharedMemorySize, smem);

    prepass_kernel<<<(NB * PTS) / 512, 512>>>(grid);      // 784 blocks
    patches_kernel<<<NB * (CC / 2), THREADS, smem>>>(fm, out);
}